// round 15
// baseline (speedup 1.0000x reference)
#include <cuda_runtime.h>
#include <cuda.h>
#include <cuda_bf16.h>
#include <math.h>
#include <stdint.h>

#define Bn    16
#define Cin   128
#define HW    1024
#define MID   512
#define OUTC  111
#define NE    4
#define BOUT  (Bn*OUTC)
#define NTOT  (49*MID*Cin)
#define APW   (49*4*8*512)      // A words per sample per plane (uint32)
#define XPW2  (38*32*40)        // x words per sample per plane

__device__ __align__(1024) float    g_routing[Bn*NE];
__device__ __align__(1024) float    g_wm[(size_t)NE*NTOT];        // [e][t][o][ic]
__device__ __align__(1024) uint32_t g_ah[(size_t)Bn*APW];         // A hi digit planes
__device__ __align__(1024) uint32_t g_al[(size_t)Bn*APW];         // A lo
__device__ __align__(1024) uint32_t g_xh[(size_t)Bn*XPW2];        // x hi [b][ph][k4(32)][w40]
__device__ __align__(1024) uint32_t g_xl[(size_t)Bn*XPW2];        // x lo
__device__ __align__(1024) float    g_y[(size_t)Bn*MID*HW];
__device__ float g_ymean[Bn*MID];
__device__ float g_mf[Bn*HW];
__device__ float g_ca[Bn*MID];
__device__ unsigned int g_maxA;   // bits of max|wm|
__device__ unsigned int g_maxB;   // bits of max|x|

#define QSCALE 16200.0f
#define FMAGIC 12582912.0f      // 2^23 + 2^22

__device__ __forceinline__ uint32_t smem_u32(const void* p){
    uint32_t a; asm("{ .reg .u64 t; cvta.to.shared.u64 t, %1; cvt.u32.u64 %0, t; }"
                    : "=r"(a) : "l"(p)); return a;
}
__device__ __forceinline__ void cp16(uint32_t dst, const void* src){
    asm volatile("cp.async.cg.shared.global [%0], [%1], 16;" :: "r"(dst), "l"(src));
}
__device__ __forceinline__ void cpcommit(){
    asm volatile("cp.async.commit_group;" ::: "memory");
}
template<int N> __device__ __forceinline__ void cpwait(){
    asm volatile("cp.async.wait_group %0;" :: "n"(N) : "memory");
}
#define LDS128(r0,r1,r2,r3,addr) \
    asm volatile("ld.shared.v4.b32 {%0,%1,%2,%3}, [%4];" \
        : "=r"(r0),"=r"(r1),"=r"(r2),"=r"(r3) : "r"(addr))
#define LDS32(r0,addr) \
    asm volatile("ld.shared.b32 %0, [%1];" : "=r"(r0) : "r"(addr))
#define MMA_S8(d, a, b2) \
    asm volatile("mma.sync.aligned.m16n8k32.row.col.s32.s8.s8.s32 " \
        "{%0,%1,%2,%3}, {%4,%5,%6,%7}, {%8,%9}, {%0,%1,%2,%3};" \
        : "+r"((d)[0]),"+r"((d)[1]),"+r"((d)[2]),"+r"((d)[3]) \
        : "r"((a)[0]),"r"((a)[1]),"r"((a)[2]),"r"((a)[3]), \
          "r"((b2)[0]),"r"((b2)[1]))

// packed f32x2 helpers
__device__ __forceinline__ uint64_t pkf2(float lo, float hi){
    uint64_t r; asm("mov.b64 %0, {%1, %2};" : "=l"(r) : "f"(lo), "f"(hi)); return r;
}
__device__ __forceinline__ uint64_t ffma2(uint64_t a, uint64_t b, uint64_t c){
    uint64_t d; asm("fma.rn.f32x2 %0, %1, %2, %3;" : "=l"(d) : "l"(a), "l"(b), "l"(c));
    return d;
}
__device__ __forceinline__ void upk2(uint64_t v, uint32_t& a, uint32_t& b){
    asm("mov.b64 {%0, %1}, %2;" : "=r"(a), "=r"(b) : "l"(v));
}

__device__ __forceinline__ void q2d(float v, float inv, int& hi, int& lo){
    int q = __float2int_rn(v*inv);
    hi = (q + 64) >> 7;
    lo = q - (hi << 7);
}
__device__ __forceinline__ uint32_t pk4(int b0, int b1, int b2, int b3){
    return (uint32_t)(b0 & 0xFF) | ((uint32_t)(b1 & 0xFF) << 8) |
           ((uint32_t)(b2 & 0xFF) << 16) | ((uint32_t)(b3 & 0xFF) << 24);
}
__device__ __forceinline__ void wmax_red(float m, unsigned int* dst){
    #pragma unroll
    for (int off = 16; off; off >>= 1)
        m = fmaxf(m, __shfl_xor_sync(0xffffffffu, m, off));
    if ((threadIdx.x & 31) == 0) atomicMax(dst, __float_as_uint(m));
}

__global__ void init_kernel(float* out) {
    int i = blockIdx.x*256 + threadIdx.x;
    if (i < BOUT)   out[i] = 0.f;
    if (i < Bn*MID) g_ymean[i] = 0.f;
    if (blockIdx.x == 0 && threadIdx.x == 0) { g_maxA = 0u; g_maxB = 0u; }
}

__global__ void xp_zero() {
    size_t i = (size_t)blockIdx.x*256 + threadIdx.x;
    if (i < (size_t)Bn*XPW2) { g_xh[i] = 0u; g_xl[i] = 0u; }
}

__global__ void routing_kernel(const float* __restrict__ x,
                               const float* __restrict__ rw,
                               const float* __restrict__ rb) {
    int b = blockIdx.x;
    __shared__ float pooled[Cin];
    __shared__ float logit[NE];
    int t = threadIdx.x, warp = t >> 5, lane = t & 31;
    const float* xb = x + (size_t)b*Cin*HW;
    float mx = 0.f;
    for (int c = warp; c < Cin; c += 8) {
        float s = 0.f;
        for (int i = lane; i < HW; i += 32) {
            float v = xb[c*HW + i];
            s += v; mx = fmaxf(mx, fabsf(v));
        }
        #pragma unroll
        for (int off = 16; off; off >>= 1) s += __shfl_down_sync(0xffffffffu, s, off);
        if (lane == 0) pooled[c] = s * (1.0f/HW);
    }
    wmax_red(mx, &g_maxB);
    __syncthreads();
    if (t < NE) {
        float s = rb[t];
        for (int c = 0; c < Cin; c++) s += pooled[c] * rw[t*Cin + c];
        logit[t] = s;
    }
    __syncthreads();
    if (t == 0) {
        float m = fmaxf(fmaxf(logit[0],logit[1]), fmaxf(logit[2],logit[3]));
        float e[NE]; float sum = 0.f;
        #pragma unroll
        for (int i = 0; i < NE; i++) { e[i] = expf(logit[i]-m); sum += e[i]; }
        float inv = 1.f/sum;
        #pragma unroll
        for (int i = 0; i < NE; i++) g_routing[b*NE + i] = e[i]*inv;
    }
}

__global__ void merge_kernel(const float* __restrict__ w3,
                             const float* __restrict__ w5,
                             const float* __restrict__ w7) {
    int o = blockIdx.x, e = blockIdx.y;
    __shared__ float s7[Cin*49];
    __shared__ float s5[Cin*25];
    __shared__ float s3[Cin*9];
    size_t base = ((size_t)e*MID + o)*Cin;
    int t = threadIdx.x;
    for (int i = t; i < Cin*49; i += 256) s7[i] = w7[base*49 + i];
    for (int i = t; i < Cin*25; i += 256) s5[i] = w5[base*25 + i];
    for (int i = t; i < Cin*9;  i += 256) s3[i] = w3[base*9  + i];
    __syncthreads();
    float mx = 0.f;
    for (int i = t; i < 49*Cin; i += 256) {
        int tap = i >> 7, ic = i & 127;
        int ty = tap / 7, tx = tap % 7;
        float v = s7[ic*49 + tap];
        if ((unsigned)(ty-1) < 5u && (unsigned)(tx-1) < 5u) v += s5[ic*25 + (ty-1)*5 + (tx-1)];
        if ((unsigned)(ty-2) < 3u && (unsigned)(tx-2) < 3u) v += s3[ic*9  + (ty-2)*3 + (tx-2)];
        g_wm[(((size_t)e*49 + tap)*MID + o)*Cin + ic] = v;
        mx = fmaxf(mx, fabsf(v));
    }
    wmax_red(mx, &g_maxA);
}

__global__ void xp_fill(const float* __restrict__ x) {
    int b = blockIdx.y, h = blockIdx.x;
    int tid = threadIdx.x;
    int w = tid & 31, grp = tid >> 5;
    float inv = QSCALE / __uint_as_float(g_maxB);
    #pragma unroll
    for (int i = 0; i < 8; i++) {
        int k4 = grp*8 + i;
        int hh[4], ll[4];
        #pragma unroll
        for (int j = 0; j < 4; j++) {
            float v = x[((size_t)b*Cin + 4*k4 + j)*HW + h*32 + w];
            q2d(v, inv, hh[j], ll[j]);
        }
        size_t d = (((size_t)b*38 + h + 3)*32 + k4)*40 + w + 3;
        g_xh[d] = pk4(hh[0], hh[1], hh[2], hh[3]);
        g_xl[d] = pk4(ll[0], ll[1], ll[2], ll[3]);
    }
}

// mix experts -> int8 digit planes; b-loop split 4x across grid.z
#define FM_SMEM (4*128*33*4)
__global__ void __launch_bounds__(256)
fragmix_kernel() {
    extern __shared__ float ws[];   // [e][o(128)][33]
    __shared__ float r[Bn*NE];
    int t = blockIdx.x;
    int icq = blockIdx.y & 3, mtb4 = blockIdx.y >> 2;
    int bq = blockIdx.z;            // 4 samples per block: b = bq*4 .. bq*4+3
    int tid = threadIdx.x;
    if (tid < Bn*NE) r[tid] = g_routing[tid];
    for (int idx = tid; idx < 4*128*32; idx += 256) {
        int e = idx >> 12, ol = (idx >> 5) & 127, icl = idx & 31;
        ws[(e*128 + ol)*33 + icl] =
            g_wm[(((size_t)e*49 + t)*MID + mtb4*128 + ol)*Cin + icq*32 + icl];
    }
    __syncthreads();
    float invq = QSCALE / __uint_as_float(g_maxA);
    uint64_t IQ2 = pkf2(invq, invq);
    uint64_t IH2 = pkf2(invq*(1.0f/128.0f), invq*(1.0f/128.0f));
    uint64_t M2  = pkf2(FMAGIC, FMAGIC);

    int half = tid >> 7, mt = (tid >> 5) & 3, ln = tid & 31;
    int c = ln & 3, rl = ln >> 2;
    int oL = half*64 + mt*16 + rl;
    int kb = 4*c;
    uint64_t evp[8][4];
    #pragma unroll
    for (int e = 0; e < 4; e++) {
        int b0 = (e*128 + oL)*33;
        int b1 = b0 + 8*33;
        evp[0][e] = pkf2(ws[b0+kb],      ws[b0+kb+1]);
        evp[1][e] = pkf2(ws[b0+kb+2],    ws[b0+kb+3]);
        evp[2][e] = pkf2(ws[b1+kb],      ws[b1+kb+1]);
        evp[3][e] = pkf2(ws[b1+kb+2],    ws[b1+kb+3]);
        evp[4][e] = pkf2(ws[b0+16+kb],   ws[b0+16+kb+1]);
        evp[5][e] = pkf2(ws[b0+16+kb+2], ws[b0+16+kb+3]);
        evp[6][e] = pkf2(ws[b1+16+kb],   ws[b1+16+kb+1]);
        evp[7][e] = pkf2(ws[b1+16+kb+2], ws[b1+16+kb+3]);
    }
    size_t chunk = ((size_t)t*4 + icq)*8 + mtb4*2 + half;
    size_t dstw = chunk*512 + (size_t)(mt*32 + ln)*4;
    #pragma unroll
    for (int bi = 0; bi < 4; bi++) {
        int b = bq*4 + bi;
        uint64_t rp0 = pkf2(r[b*4+0], r[b*4+0]);
        uint64_t rp1 = pkf2(r[b*4+1], r[b*4+1]);
        uint64_t rp2 = pkf2(r[b*4+2], r[b*4+2]);
        uint64_t rp3 = pkf2(r[b*4+3], r[b*4+3]);
        uint32_t hw[4], lw[4];
        #pragma unroll
        for (int w = 0; w < 4; w++) {
            uint32_t hb[4], lb[4];
            #pragma unroll
            for (int pp = 0; pp < 2; pp++) {
                int p = w*2 + pp;
                uint64_t v2 = ffma2(evp[p][3], rp3, 0ull);
                v2 = ffma2(evp[p][2], rp2, v2);
                v2 = ffma2(evp[p][1], rp1, v2);
                v2 = ffma2(evp[p][0], rp0, v2);
                uint64_t hf2 = ffma2(v2, IH2, M2);
                uint64_t qf2 = ffma2(v2, IQ2, M2);
                uint32_t h0, h1, q0, q1;
                upk2(hf2, h0, h1);
                upk2(qf2, q0, q1);
                hb[pp*2]   = h0;
                hb[pp*2+1] = h1;
                lb[pp*2]   = q0 - 128u*h0;
                lb[pp*2+1] = q1 - 128u*h1;
            }
            hw[w] = __byte_perm(__byte_perm(hb[0], hb[1], 0x0040),
                                __byte_perm(hb[2], hb[3], 0x0040), 0x5410);
            lw[w] = __byte_perm(__byte_perm(lb[0], lb[1], 0x0040),
                                __byte_perm(lb[2], lb[3], 0x0040), 0x5410);
        }
        *(uint4*)&g_ah[(size_t)b*APW + dstw] = make_uint4(hw[0], hw[1], hw[2], hw[3]);
        *(uint4*)&g_al[(size_t)b*APW + dstw] = make_uint4(lw[0], lw[1], lw[2], lw[3]);
    }
}

// ---------------- conv: int8 IMMA, M=64 N=256 per CTA, 512 threads -------------
#define A_LO      2048
#define A_STG     4096
#define A_ALL     (4*A_STG)
#define B_ISTR    328
#define B_STG     10496
#define B_STG2    (2*B_STG)
#define SMEM_CONV (A_ALL + 2*B_STG2)

__global__ void __launch_bounds__(512, 1)
conv_mma() {
    extern __shared__ __align__(16) char smem[];
    uint32_t sb = smem_u32(smem);
    int tid = threadIdx.x, wid = tid >> 5, lane = tid & 31;
    int c = lane & 3, rl = lane >> 2;
    int wm = wid & 1, wn = wid >> 1;
    int mtb = blockIdx.x, nt = blockIdx.y, b = blockIdx.z;

    const uint32_t* Abh = g_ah + (size_t)b*APW;
    const uint32_t* Abl = g_al + (size_t)b*APW;

    int acc1[2][4][4], acc2[2][4][4];
    #pragma unroll
    for (int mi = 0; mi < 2; mi++)
        #pragma unroll
        for (int ni = 0; ni < 4; ni++)
            #pragma unroll
            for (int q = 0; q < 4; q++) { acc1[mi][ni][q] = 0; acc2[mi][ni][q] = 0; }

    uint32_t bb[4];
    #pragma unroll
    for (int ni = 0; ni < 4; ni++)
        bb[ni] = (uint32_t)((wn*40 + ni*8 + rl) << 2);

    auto issueA = [&](int m, int buf) {
        if (tid >= 256) return;
        int jj = m/7, dxx = m - jj*7;
        int t = (jj >> 2)*7 + dxx, icq = jj & 3;
        size_t chunk = ((size_t)t*4 + icq)*8 + mtb;
        int half = tid >> 7, u = tid & 127;
        const uint32_t* src = (half ? Abl : Abh) + chunk*512 + (size_t)u*4;
        uint32_t dst = sb + buf*A_STG + (uint32_t)(half*A_LO) + (uint32_t)(u*16);
        cp16(dst, src);
    };
    auto issueB = [&](int jj, int buf) {
        int dy = jj >> 2, icq = jj & 3;
        for (int task = tid; task < 1280; task += 512) {
            int plane = task >= 640;
            int v = plane ? task - 640 : task;
            int k4 = v / 80, rem = v % 80;
            int h = rem / 10, q = rem % 10;
            size_t srcw = (((size_t)(b*38 + nt*8 + h + dy))*32 + icq*8 + k4)*40 + q*4;
            const uint32_t* src = plane ? (g_xl + srcw) : (g_xh + srcw);
            uint32_t dst = sb + A_ALL + buf*B_STG2 + (uint32_t)(plane*B_STG)
                         + (uint32_t)(k4*1312 + h*160 + q*16);
            cp16(dst, src);
        }
    };

    issueB(0, 0); issueA(0, 0); cpcommit();
    issueA(1, 1); cpcommit();
    issueA(2, 2); cpcommit();

    int j = 0, dx = 0;
    for (int m = 0; m < 196; m++) {
        if (m < 194)        cpwait<2>();
        else if (m == 194)  cpwait<1>();
        else                cpwait<0>();
        __syncthreads();
        {
            bool any = false;
            if (m + 3 < 196) { issueA(m + 3, (m + 3) & 3); any = true; }
            if (dx == 0 && j < 27) { issueB(j + 1, (j + 1) & 1); any = true; }
            if (any) cpcommit();
        }

        uint32_t aS  = sb + (m & 3)*A_STG;
        uint32_t bSh = sb + A_ALL + (j & 1)*B_STG2 + (uint32_t)(dx << 2);
        uint32_t bSl = bSh + B_STG;
        uint32_t k0o = (uint32_t)(c*1312), k1o = k0o + 4*1312;

        uint32_t bh[4][2], bl[4][2];
        #pragma unroll
        for (int ni = 0; ni < 4; ni++) {
            LDS32(bh[ni][0], bSh + k0o + bb[ni]);
            LDS32(bh[ni][1], bSh + k1o + bb[ni]);
            LDS32(bl[ni][0], bSl + k0o + bb[ni]);
            LDS32(bl[ni][1], bSl + k1o + bb[ni]);
        }
        uint32_t af[2][4];
        #pragma unroll
        for (int mi = 0; mi < 2; mi++)
            LDS128(af[mi][0], af[mi][1], af[mi][2], af[mi][3],
                   aS + (uint32_t)((((wm*2 + mi)*32) + lane) << 4));
        #pragma unroll
        for (int mi = 0; mi < 2; mi++)
            #pragma unroll
            for (int ni = 0; ni < 4; ni++) {
                MMA_S8(acc1[mi][ni], af[mi], bh[ni]);
                MMA_S8(acc2[mi][ni], af[mi], bl[ni]);
            }
        #pragma unroll
        for (int mi = 0; mi < 2; mi++)
            LDS128(af[mi][0], af[mi][1], af[mi][2], af[mi][3],
                   aS + A_LO + (uint32_t)((((wm*2 + mi)*32) + lane) << 4));
        #pragma unroll
        for (int mi = 0; mi < 2; mi++)
            #pragma unroll
            for (int ni = 0; ni < 4; ni++)
                MMA_S8(acc2[mi][ni], af[mi], bh[ni]);

        if (++dx == 7) { dx = 0; j++; }
    }

    float S = (__uint_as_float(g_maxA)/QSCALE) * (__uint_as_float(g_maxB)/QSCALE);
    int o0 = mtb*64 + wm*32;
    int p0 = nt*256 + wn*32;
    #pragma unroll
    for (int mi = 0; mi < 2; mi++) {
        int o = o0 + mi*16 + rl;
        float s0 = 0.f, s1 = 0.f;
        float* y0 = g_y + ((size_t)b*MID + o)*HW;
        float* y1 = g_y + ((size_t)b*MID + o + 8)*HW;
        #pragma unroll
        for (int ni = 0; ni < 4; ni++) {
            int p = p0 + ni*8 + 2*c;
            float2 v0, v1;
            v0.x = S*(16384.f*(float)acc1[mi][ni][0] + 128.f*(float)acc2[mi][ni][0]);
            v0.y = S*(16384.f*(float)acc1[mi][ni][1] + 128.f*(float)acc2[mi][ni][1]);
            v1.x = S*(16384.f*(float)acc1[mi][ni][2] + 128.f*(float)acc2[mi][ni][2]);
            v1.y = S*(16384.f*(float)acc1[mi][ni][3] + 128.f*(float)acc2[mi][ni][3]);
            *(float2*)(y0 + p) = v0;
            *(float2*)(y1 + p) = v1;
            s0 += v0.x + v0.y;
            s1 += v1.x + v1.y;
        }
        s0 += __shfl_xor_sync(0xffffffffu, s0, 1);
        s0 += __shfl_xor_sync(0xffffffffu, s0, 2);
        s1 += __shfl_xor_sync(0xffffffffu, s1, 1);
        s1 += __shfl_xor_sync(0xffffffffu, s1, 2);
        if (c == 0) {
            atomicAdd(&g_ymean[b*MID + o], s0);
            atomicAdd(&g_ymean[b*MID + o + 8], s1);
        }
    }
}

__global__ void ca_kernel(const float* __restrict__ fc1w, const float* __restrict__ fc1b,
                          const float* __restrict__ fc2w, const float* __restrict__ fc2b) {
    int b = blockIdx.x, t = threadIdx.x;
    __shared__ float m[MID];
    __shared__ float h[32];
    m[t] = g_ymean[b*MID + t] * (1.0f/HW);
    __syncthreads();
    if (t < 32) {
        float s = fc1b[t];
        for (int c = 0; c < MID; c++) s += fc1w[t*MID + c] * m[c];
        h[t] = fmaxf(s, 0.f);
    }
    __syncthreads();
    float s = fc2b[t];
    #pragma unroll
    for (int j = 0; j < 32; j++) s += fc2w[t*32 + j] * h[j];
    g_ca[b*MID + t] = 1.f/(1.f + expf(-s));
}

__global__ void mf_kernel(const float* __restrict__ mask,
                          const float* __restrict__ mpw,
                          const float* __restrict__ mpb) {
    __shared__ float w[Cin];
    int t = threadIdx.x;
    if (t < Cin) w[t] = mpw[t];
    __syncthreads();
    int b = blockIdx.y;
    int p = blockIdx.x*256 + t;
    const float* mb = mask + (size_t)b*Cin*HW + p;
    float s = mpb[0];
    #pragma unroll 8
    for (int c = 0; c < Cin; c++) s += mb[c*HW] * w[c];
    g_mf[b*HW + p] = s;
}

__global__ void __launch_bounds__(128)
final_kernel(const float* __restrict__ predw, float* __restrict__ out) {
    int b = blockIdx.x, pt = blockIdx.y, oq = blockIdx.z;
    int t = threadIdx.x;
    int p = pt*128 + t;
    int ob = oq*28;

    __shared__ float pw[64][28];
    float4 acc[7];
    #pragma unroll
    for (int j = 0; j < 7; j++) acc[j] = make_float4(0.f,0.f,0.f,0.f);

    for (int c0 = 0; c0 < MID; c0 += 64) {
        __syncthreads();
        for (int i = t; i < 64*28; i += 128) {
            int cl = i / 28, o = ob + i % 28;
            float v = 0.f;
            if (o < OUTC) v = predw[o*MID + c0 + cl] * g_ca[b*MID + c0 + cl];
            pw[cl][i % 28] = v;
        }
        __syncthreads();
        const float* yb = g_y + ((size_t)b*MID + c0)*HW + p;
        #pragma unroll 4
        for (int cl = 0; cl < 64; cl++) {
            float yv = yb[(size_t)cl*HW];
            const float4* pw4 = (const float4*)pw[cl];
            #pragma unroll
            for (int j = 0; j < 7; j++) {
                float4 w4 = pw4[j];
                acc[j].x += w4.x*yv; acc[j].y += w4.y*yv;
                acc[j].z += w4.z*yv; acc[j].w += w4.w*yv;
            }
        }
    }

    float mf = g_mf[b*HW + p];
    float* dbase = out + BOUT + ((size_t)b*OUTC)*HW + p;
    float* cnt   = out + b*OUTC;
    int lane = t & 31;

#define EMIT(OO, AV) do {                                              \
        if ((OO) < OUTC) {                                             \
            float dv = 1.f/(1.f + expf(-(AV)*mf));                     \
            dbase[(size_t)(OO)*HW] = dv;                               \
            float s_ = dv;                                             \
            s_ += __shfl_down_sync(0xffffffffu, s_, 16);               \
            s_ += __shfl_down_sync(0xffffffffu, s_, 8);                \
            s_ += __shfl_down_sync(0xffffffffu, s_, 4);                \
            s_ += __shfl_down_sync(0xffffffffu, s_, 2);                \
            s_ += __shfl_down_sync(0xffffffffu, s_, 1);                \
            if (lane == 0) atomicAdd(&cnt[(OO)], s_);                  \
        }                                                              \
    } while (0)

    #pragma unroll
    for (int j = 0; j < 7; j++) {
        float4 a = acc[j];
        EMIT(ob + 4*j+0, a.x); EMIT(ob + 4*j+1, a.y);
        EMIT(ob + 4*j+2, a.z); EMIT(ob + 4*j+3, a.w);
    }
#undef EMIT
}

extern "C" void kernel_launch(void* const* d_in, const int* in_sizes, int n_in,
                              void* d_out, int out_size) {
    const float* x        = (const float*)d_in[0];
    const float* mask     = (const float*)d_in[1];
    const float* w3       = (const float*)d_in[2];
    const float* w5       = (const float*)d_in[3];
    const float* w7       = (const float*)d_in[4];
    const float* router_w = (const float*)d_in[5];
    const float* router_b = (const float*)d_in[6];
    const float* fc1_w    = (const float*)d_in[7];
    const float* fc1_b    = (const float*)d_in[8];
    const float* fc2_w    = (const float*)d_in[9];
    const float* fc2_b    = (const float*)d_in[10];
    const float* mpw      = (const float*)d_in[11];
    const float* mpb      = (const float*)d_in[12];
    const float* pred_w   = (const float*)d_in[13];
    float* out = (float*)d_out;

    // order matters: fragmix is the 4th launch -> captured by ncu (-s window)
    init_kernel<<<32, 256>>>(out);
    routing_kernel<<<Bn, 256>>>(x, router_w, router_b);
    merge_kernel<<<dim3(MID, NE), 256>>>(w3, w5, w7);

    cudaFuncSetAttribute(fragmix_kernel, cudaFuncAttributeMaxDynamicSharedMemorySize, FM_SMEM);
    fragmix_kernel<<<dim3(49, 16, 4), 256, FM_SMEM>>>();

    {
        size_t n = (size_t)Bn*XPW2;
        xp_zero<<<(int)((n + 255)/256), 256>>>();
    }
    xp_fill<<<dim3(32, Bn), 128>>>(x);

    cudaFuncSetAttribute(conv_mma, cudaFuncAttributeMaxDynamicSharedMemorySize, SMEM_CONV);
    conv_mma<<<dim3(8, 4, Bn), 512, SMEM_CONV>>>();

    mf_kernel<<<dim3(4, Bn), 256>>>(mask, mpw, mpb);
    ca_kernel<<<Bn, 512>>>(fc1_w, fc1_b, fc2_w, fc2_b);
    final_kernel<<<dim3(Bn, 8, 4), 128>>>(pred_w, out);
}

// round 16
// speedup vs baseline: 1.1193x; 1.1193x over previous
#include <cuda_runtime.h>
#include <cuda.h>
#include <cuda_bf16.h>
#include <math.h>
#include <stdint.h>

#define Bn    16
#define Cin   128
#define HW    1024
#define MID   512
#define OUTC  111
#define NE    4
#define BOUT  (Bn*OUTC)
#define NTOT  (49*MID*Cin)
#define APW   (49*4*8*512)
#define XPW2  (38*32*40)

__device__ __align__(1024) float    g_routing[Bn*NE];
__device__ __align__(1024) float    g_wm[(size_t)NE*NTOT];
__device__ __align__(1024) uint32_t g_ah[(size_t)Bn*APW];
__device__ __align__(1024) uint32_t g_al[(size_t)Bn*APW];
__device__ __align__(1024) uint32_t g_xh[(size_t)Bn*XPW2];
__device__ __align__(1024) uint32_t g_xl[(size_t)Bn*XPW2];
__device__ __align__(1024) float    g_y[(size_t)Bn*MID*HW];
__device__ float g_ymean[Bn*MID];
__device__ float g_mf[Bn*HW];
__device__ float g_ca[Bn*MID];
__device__ unsigned int g_maxA;
__device__ unsigned int g_maxB;

#define QSCALE 16200.0f
#define FMAGIC 12582912.0f

__device__ __forceinline__ uint32_t smem_u32(const void* p){
    uint32_t a; asm("{ .reg .u64 t; cvta.to.shared.u64 t, %1; cvt.u32.u64 %0, t; }"
                    : "=r"(a) : "l"(p)); return a;
}
__device__ __forceinline__ void cp16(uint32_t dst, const void* src){
    asm volatile("cp.async.cg.shared.global [%0], [%1], 16;" :: "r"(dst), "l"(src));
}
__device__ __forceinline__ void cpcommit(){
    asm volatile("cp.async.commit_group;" ::: "memory");
}
template<int N> __device__ __forceinline__ void cpwait(){
    asm volatile("cp.async.wait_group %0;" :: "n"(N) : "memory");
}
#define LDS128(r0,r1,r2,r3,addr) \
    asm volatile("ld.shared.v4.b32 {%0,%1,%2,%3}, [%4];" \
        : "=r"(r0),"=r"(r1),"=r"(r2),"=r"(r3) : "r"(addr))
#define LDS32(r0,addr) \
    asm volatile("ld.shared.b32 %0, [%1];" : "=r"(r0) : "r"(addr))
#define MMA_S8(d, a, b2) \
    asm volatile("mma.sync.aligned.m16n8k32.row.col.s32.s8.s8.s32 " \
        "{%0,%1,%2,%3}, {%4,%5,%6,%7}, {%8,%9}, {%0,%1,%2,%3};" \
        : "+r"((d)[0]),"+r"((d)[1]),"+r"((d)[2]),"+r"((d)[3]) \
        : "r"((a)[0]),"r"((a)[1]),"r"((a)[2]),"r"((a)[3]), \
          "r"((b2)[0]),"r"((b2)[1]))

__device__ __forceinline__ uint64_t pkf2(float lo, float hi){
    uint64_t r; asm("mov.b64 %0, {%1, %2};" : "=l"(r) : "f"(lo), "f"(hi)); return r;
}
__device__ __forceinline__ uint64_t ffma2(uint64_t a, uint64_t b, uint64_t c){
    uint64_t d; asm("fma.rn.f32x2 %0, %1, %2, %3;" : "=l"(d) : "l"(a), "l"(b), "l"(c));
    return d;
}
__device__ __forceinline__ void upk2(uint64_t v, uint32_t& a, uint32_t& b){
    asm("mov.b64 {%0, %1}, %2;" : "=r"(a), "=r"(b) : "l"(v));
}
__device__ __forceinline__ void q2d(float v, float inv, int& hi, int& lo){
    int q = __float2int_rn(v*inv);
    hi = (q + 64) >> 7;
    lo = q - (hi << 7);
}
__device__ __forceinline__ uint32_t pk4(int b0, int b1, int b2, int b3){
    return (uint32_t)(b0 & 0xFF) | ((uint32_t)(b1 & 0xFF) << 8) |
           ((uint32_t)(b2 & 0xFF) << 16) | ((uint32_t)(b3 & 0xFF) << 24);
}
__device__ __forceinline__ void wmax_red(float m, unsigned int* dst){
    #pragma unroll
    for (int off = 16; off; off >>= 1)
        m = fmaxf(m, __shfl_xor_sync(0xffffffffu, m, off));
    if ((threadIdx.x & 31) == 0) atomicMax(dst, __float_as_uint(m));
}

// ---- prep0: init out/ymean/maxes + zero x planes (fused) --------------------
__global__ void prep0_kernel(float* out) {
    size_t i = (size_t)blockIdx.x*256 + threadIdx.x;
    if (i < BOUT)   out[i] = 0.f;
    if (i < Bn*MID) g_ymean[i] = 0.f;
    if (i == 0) { g_maxA = 0u; g_maxB = 0u; }
    if (i < (size_t)Bn*XPW2) { g_xh[i] = 0u; g_xl[i] = 0u; }
}

// ---- prep1: routing (blocks 0..15) + merge (blocks 16..2063), fused ---------
__global__ void __launch_bounds__(256)
prep1_kernel(const float* __restrict__ x,
             const float* __restrict__ rw, const float* __restrict__ rb,
             const float* __restrict__ w3, const float* __restrict__ w5,
             const float* __restrict__ w7) {
    int bx = blockIdx.x;
    int t = threadIdx.x;
    if (bx < Bn) {
        int b = bx;
        __shared__ float pooled[Cin];
        __shared__ float logit[NE];
        int warp = t >> 5, lane = t & 31;
        const float* xb = x + (size_t)b*Cin*HW;
        float mx = 0.f;
        for (int c = warp; c < Cin; c += 8) {
            float s = 0.f;
            for (int i = lane; i < HW; i += 32) {
                float v = xb[c*HW + i];
                s += v; mx = fmaxf(mx, fabsf(v));
            }
            #pragma unroll
            for (int off = 16; off; off >>= 1) s += __shfl_down_sync(0xffffffffu, s, off);
            if (lane == 0) pooled[c] = s * (1.0f/HW);
        }
        wmax_red(mx, &g_maxB);
        __syncthreads();
        if (t < NE) {
            float s = rb[t];
            for (int c = 0; c < Cin; c++) s += pooled[c] * rw[t*Cin + c];
            logit[t] = s;
        }
        __syncthreads();
        if (t == 0) {
            float m = fmaxf(fmaxf(logit[0],logit[1]), fmaxf(logit[2],logit[3]));
            float e[NE]; float sum = 0.f;
            #pragma unroll
            for (int i = 0; i < NE; i++) { e[i] = expf(logit[i]-m); sum += e[i]; }
            float inv = 1.f/sum;
            #pragma unroll
            for (int i = 0; i < NE; i++) g_routing[b*NE + i] = e[i]*inv;
        }
    } else {
        int idx = bx - Bn;
        int o = idx & 511, e = idx >> 9;
        __shared__ float s7[Cin*49];
        __shared__ float s5[Cin*25];
        __shared__ float s3[Cin*9];
        size_t base = ((size_t)e*MID + o)*Cin;
        for (int i = t; i < Cin*49; i += 256) s7[i] = w7[base*49 + i];
        for (int i = t; i < Cin*25; i += 256) s5[i] = w5[base*25 + i];
        for (int i = t; i < Cin*9;  i += 256) s3[i] = w3[base*9  + i];
        __syncthreads();
        float mx = 0.f;
        for (int i = t; i < 49*Cin; i += 256) {
            int tap = i >> 7, ic = i & 127;
            int ty = tap / 7, tx = tap % 7;
            float v = s7[ic*49 + tap];
            if ((unsigned)(ty-1) < 5u && (unsigned)(tx-1) < 5u) v += s5[ic*25 + (ty-1)*5 + (tx-1)];
            if ((unsigned)(ty-2) < 3u && (unsigned)(tx-2) < 3u) v += s3[ic*9  + (ty-2)*3 + (tx-2)];
            g_wm[(((size_t)e*49 + tap)*MID + o)*Cin + ic] = v;
            mx = fmaxf(mx, fabsf(v));
        }
        wmax_red(mx, &g_maxA);
    }
}

// ---- prep2: fragmix (blocks 0..783, serial b) + xp_fill (784..1295), fused --
#define FM_SMEM (4*128*33*4)
__global__ void __launch_bounds__(256)
prep2_kernel(const float* __restrict__ x) {
    extern __shared__ float ws[];
    int bx = blockIdx.x;
    int tid = threadIdx.x;
    if (bx < 784) {
        __shared__ float r[Bn*NE];
        int t = bx % 49, yy = bx / 49;
        int icq = yy & 3, mtb4 = yy >> 2;
        if (tid < Bn*NE) r[tid] = g_routing[tid];
        for (int idx = tid; idx < 4*128*32; idx += 256) {
            int e = idx >> 12, ol = (idx >> 5) & 127, icl = idx & 31;
            ws[(e*128 + ol)*33 + icl] =
                g_wm[(((size_t)e*49 + t)*MID + mtb4*128 + ol)*Cin + icq*32 + icl];
        }
        __syncthreads();
        float invq = QSCALE / __uint_as_float(g_maxA);
        uint64_t IQ2 = pkf2(invq, invq);
        uint64_t IH2 = pkf2(invq*(1.0f/128.0f), invq*(1.0f/128.0f));
        uint64_t M2  = pkf2(FMAGIC, FMAGIC);

        int half = tid >> 7, mt = (tid >> 5) & 3, ln = tid & 31;
        int c = ln & 3, rl = ln >> 2;
        int oL = half*64 + mt*16 + rl;
        int kb = 4*c;
        uint64_t evp[8][4];
        #pragma unroll
        for (int e = 0; e < 4; e++) {
            int b0 = (e*128 + oL)*33;
            int b1 = b0 + 8*33;
            evp[0][e] = pkf2(ws[b0+kb],      ws[b0+kb+1]);
            evp[1][e] = pkf2(ws[b0+kb+2],    ws[b0+kb+3]);
            evp[2][e] = pkf2(ws[b1+kb],      ws[b1+kb+1]);
            evp[3][e] = pkf2(ws[b1+kb+2],    ws[b1+kb+3]);
            evp[4][e] = pkf2(ws[b0+16+kb],   ws[b0+16+kb+1]);
            evp[5][e] = pkf2(ws[b0+16+kb+2], ws[b0+16+kb+3]);
            evp[6][e] = pkf2(ws[b1+16+kb],   ws[b1+16+kb+1]);
            evp[7][e] = pkf2(ws[b1+16+kb+2], ws[b1+16+kb+3]);
        }
        size_t chunk = ((size_t)t*4 + icq)*8 + mtb4*2 + half;
        size_t dstw = chunk*512 + (size_t)(mt*32 + ln)*4;
        #pragma unroll
        for (int b = 0; b < Bn; b++) {
            uint64_t rp0 = pkf2(r[b*4+0], r[b*4+0]);
            uint64_t rp1 = pkf2(r[b*4+1], r[b*4+1]);
            uint64_t rp2 = pkf2(r[b*4+2], r[b*4+2]);
            uint64_t rp3 = pkf2(r[b*4+3], r[b*4+3]);
            uint32_t hw[4], lw[4];
            #pragma unroll
            for (int w = 0; w < 4; w++) {
                uint32_t hb[4], lb[4];
                #pragma unroll
                for (int pp = 0; pp < 2; pp++) {
                    int p = w*2 + pp;
                    uint64_t v2 = ffma2(evp[p][3], rp3, 0ull);
                    v2 = ffma2(evp[p][2], rp2, v2);
                    v2 = ffma2(evp[p][1], rp1, v2);
                    v2 = ffma2(evp[p][0], rp0, v2);
                    uint64_t hf2 = ffma2(v2, IH2, M2);
                    uint64_t qf2 = ffma2(v2, IQ2, M2);
                    uint32_t h0, h1, q0, q1;
                    upk2(hf2, h0, h1);
                    upk2(qf2, q0, q1);
                    hb[pp*2]   = h0;
                    hb[pp*2+1] = h1;
                    lb[pp*2]   = q0 - 128u*h0;
                    lb[pp*2+1] = q1 - 128u*h1;
                }
                hw[w] = __byte_perm(__byte_perm(hb[0], hb[1], 0x0040),
                                    __byte_perm(hb[2], hb[3], 0x0040), 0x5410);
                lw[w] = __byte_perm(__byte_perm(lb[0], lb[1], 0x0040),
                                    __byte_perm(lb[2], lb[3], 0x0040), 0x5410);
            }
            *(uint4*)&g_ah[(size_t)b*APW + dstw] = make_uint4(hw[0], hw[1], hw[2], hw[3]);
            *(uint4*)&g_al[(size_t)b*APW + dstw] = make_uint4(lw[0], lw[1], lw[2], lw[3]);
        }
    } else {
        int idx = bx - 784;
        int b = idx >> 5, h = idx & 31;
        int w = tid & 31, grp = tid >> 5;       // grp 0..7
        float inv = QSCALE / __uint_as_float(g_maxB);
        #pragma unroll
        for (int i = 0; i < 4; i++) {
            int k4 = grp + i*8;
            int hh[4], ll[4];
            #pragma unroll
            for (int j = 0; j < 4; j++) {
                float v = x[((size_t)b*Cin + 4*k4 + j)*HW + h*32 + w];
                q2d(v, inv, hh[j], ll[j]);
            }
            size_t d = (((size_t)b*38 + h + 3)*32 + k4)*40 + w + 3;
            g_xh[d] = pk4(hh[0], hh[1], hh[2], hh[3]);
            g_xl[d] = pk4(ll[0], ll[1], ll[2], ll[3]);
        }
    }
}

// ---------------- conv: int8 IMMA (unchanged; now 4th launch) ----------------
#define A_LO      2048
#define A_STG     4096
#define A_ALL     (4*A_STG)
#define B_ISTR    328
#define B_STG     10496
#define B_STG2    (2*B_STG)
#define SMEM_CONV (A_ALL + 2*B_STG2)

__global__ void __launch_bounds__(512, 1)
conv_mma() {
    extern __shared__ __align__(16) char smem[];
    uint32_t sb = smem_u32(smem);
    int tid = threadIdx.x, wid = tid >> 5, lane = tid & 31;
    int c = lane & 3, rl = lane >> 2;
    int wm = wid & 1, wn = wid >> 1;
    int mtb = blockIdx.x, nt = blockIdx.y, b = blockIdx.z;

    const uint32_t* Abh = g_ah + (size_t)b*APW;
    const uint32_t* Abl = g_al + (size_t)b*APW;

    int acc1[2][4][4], acc2[2][4][4];
    #pragma unroll
    for (int mi = 0; mi < 2; mi++)
        #pragma unroll
        for (int ni = 0; ni < 4; ni++)
            #pragma unroll
            for (int q = 0; q < 4; q++) { acc1[mi][ni][q] = 0; acc2[mi][ni][q] = 0; }

    uint32_t bb[4];
    #pragma unroll
    for (int ni = 0; ni < 4; ni++)
        bb[ni] = (uint32_t)((wn*40 + ni*8 + rl) << 2);

    auto issueA = [&](int m, int buf) {
        if (tid >= 256) return;
        int jj = m/7, dxx = m - jj*7;
        int t = (jj >> 2)*7 + dxx, icq = jj & 3;
        size_t chunk = ((size_t)t*4 + icq)*8 + mtb;
        int half = tid >> 7, u = tid & 127;
        const uint32_t* src = (half ? Abl : Abh) + chunk*512 + (size_t)u*4;
        uint32_t dst = sb + buf*A_STG + (uint32_t)(half*A_LO) + (uint32_t)(u*16);
        cp16(dst, src);
    };
    auto issueB = [&](int jj, int buf) {
        int dy = jj >> 2, icq = jj & 3;
        for (int task = tid; task < 1280; task += 512) {
            int plane = task >= 640;
            int v = plane ? task - 640 : task;
            int k4 = v / 80, rem = v % 80;
            int h = rem / 10, q = rem % 10;
            size_t srcw = (((size_t)(b*38 + nt*8 + h + dy))*32 + icq*8 + k4)*40 + q*4;
            const uint32_t* src = plane ? (g_xl + srcw) : (g_xh + srcw);
            uint32_t dst = sb + A_ALL + buf*B_STG2 + (uint32_t)(plane*B_STG)
                         + (uint32_t)(k4*1312 + h*160 + q*16);
            cp16(dst, src);
        }
    };

    issueB(0, 0); issueA(0, 0); cpcommit();
    issueA(1, 1); cpcommit();
    issueA(2, 2); cpcommit();

    int j = 0, dx = 0;
    for (int m = 0; m < 196; m++) {
        if (m < 194)        cpwait<2>();
        else if (m == 194)  cpwait<1>();
        else                cpwait<0>();
        __syncthreads();
        {
            bool any = false;
            if (m + 3 < 196) { issueA(m + 3, (m + 3) & 3); any = true; }
            if (dx == 0 && j < 27) { issueB(j + 1, (j + 1) & 1); any = true; }
            if (any) cpcommit();
        }

        uint32_t aS  = sb + (m & 3)*A_STG;
        uint32_t bSh = sb + A_ALL + (j & 1)*B_STG2 + (uint32_t)(dx << 2);
        uint32_t bSl = bSh + B_STG;
        uint32_t k0o = (uint32_t)(c*1312), k1o = k0o + 4*1312;

        uint32_t bh[4][2], bl[4][2];
        #pragma unroll
        for (int ni = 0; ni < 4; ni++) {
            LDS32(bh[ni][0], bSh + k0o + bb[ni]);
            LDS32(bh[ni][1], bSh + k1o + bb[ni]);
            LDS32(bl[ni][0], bSl + k0o + bb[ni]);
            LDS32(bl[ni][1], bSl + k1o + bb[ni]);
        }
        uint32_t af[2][4];
        #pragma unroll
        for (int mi = 0; mi < 2; mi++)
            LDS128(af[mi][0], af[mi][1], af[mi][2], af[mi][3],
                   aS + (uint32_t)((((wm*2 + mi)*32) + lane) << 4));
        #pragma unroll
        for (int mi = 0; mi < 2; mi++)
            #pragma unroll
            for (int ni = 0; ni < 4; ni++) {
                MMA_S8(acc1[mi][ni], af[mi], bh[ni]);
                MMA_S8(acc2[mi][ni], af[mi], bl[ni]);
            }
        #pragma unroll
        for (int mi = 0; mi < 2; mi++)
            LDS128(af[mi][0], af[mi][1], af[mi][2], af[mi][3],
                   aS + A_LO + (uint32_t)((((wm*2 + mi)*32) + lane) << 4));
        #pragma unroll
        for (int mi = 0; mi < 2; mi++)
            #pragma unroll
            for (int ni = 0; ni < 4; ni++)
                MMA_S8(acc2[mi][ni], af[mi], bh[ni]);

        if (++dx == 7) { dx = 0; j++; }
    }

    float S = (__uint_as_float(g_maxA)/QSCALE) * (__uint_as_float(g_maxB)/QSCALE);
    int o0 = mtb*64 + wm*32;
    int p0 = nt*256 + wn*32;
    #pragma unroll
    for (int mi = 0; mi < 2; mi++) {
        int o = o0 + mi*16 + rl;
        float s0 = 0.f, s1 = 0.f;
        float* y0 = g_y + ((size_t)b*MID + o)*HW;
        float* y1 = g_y + ((size_t)b*MID + o + 8)*HW;
        #pragma unroll
        for (int ni = 0; ni < 4; ni++) {
            int p = p0 + ni*8 + 2*c;
            float2 v0, v1;
            v0.x = S*(16384.f*(float)acc1[mi][ni][0] + 128.f*(float)acc2[mi][ni][0]);
            v0.y = S*(16384.f*(float)acc1[mi][ni][1] + 128.f*(float)acc2[mi][ni][1]);
            v1.x = S*(16384.f*(float)acc1[mi][ni][2] + 128.f*(float)acc2[mi][ni][2]);
            v1.y = S*(16384.f*(float)acc1[mi][ni][3] + 128.f*(float)acc2[mi][ni][3]);
            *(float2*)(y0 + p) = v0;
            *(float2*)(y1 + p) = v1;
            s0 += v0.x + v0.y;
            s1 += v1.x + v1.y;
        }
        s0 += __shfl_xor_sync(0xffffffffu, s0, 1);
        s0 += __shfl_xor_sync(0xffffffffu, s0, 2);
        s1 += __shfl_xor_sync(0xffffffffu, s1, 1);
        s1 += __shfl_xor_sync(0xffffffffu, s1, 2);
        if (c == 0) {
            atomicAdd(&g_ymean[b*MID + o], s0);
            atomicAdd(&g_ymean[b*MID + o + 8], s1);
        }
    }
}

__global__ void ca_kernel(const float* __restrict__ fc1w, const float* __restrict__ fc1b,
                          const float* __restrict__ fc2w, const float* __restrict__ fc2b) {
    int b = blockIdx.x, t = threadIdx.x;
    __shared__ float m[MID];
    __shared__ float h[32];
    m[t] = g_ymean[b*MID + t] * (1.0f/HW);
    __syncthreads();
    if (t < 32) {
        float s = fc1b[t];
        for (int c = 0; c < MID; c++) s += fc1w[t*MID + c] * m[c];
        h[t] = fmaxf(s, 0.f);
    }
    __syncthreads();
    float s = fc2b[t];
    #pragma unroll
    for (int j = 0; j < 32; j++) s += fc2w[t*32 + j] * h[j];
    g_ca[b*MID + t] = 1.f/(1.f + expf(-s));
}

__global__ void mf_kernel(const float* __restrict__ mask,
                          const float* __restrict__ mpw,
                          const float* __restrict__ mpb) {
    __shared__ float w[Cin];
    int t = threadIdx.x;
    if (t < Cin) w[t] = mpw[t];
    __syncthreads();
    int b = blockIdx.y;
    int p = blockIdx.x*256 + t;
    const float* mb = mask + (size_t)b*Cin*HW + p;
    float s = mpb[0];
    #pragma unroll 8
    for (int c = 0; c < Cin; c++) s += mb[c*HW] * w[c];
    g_mf[b*HW + p] = s;
}

__global__ void __launch_bounds__(128)
final_kernel(const float* __restrict__ predw, float* __restrict__ out) {
    int b = blockIdx.x, pt = blockIdx.y, oq = blockIdx.z;
    int t = threadIdx.x;
    int p = pt*128 + t;
    int ob = oq*28;

    __shared__ float pw[64][28];
    float4 acc[7];
    #pragma unroll
    for (int j = 0; j < 7; j++) acc[j] = make_float4(0.f,0.f,0.f,0.f);

    for (int c0 = 0; c0 < MID; c0 += 64) {
        __syncthreads();
        for (int i = t; i < 64*28; i += 128) {
            int cl = i / 28, o = ob + i % 28;
            float v = 0.f;
            if (o < OUTC) v = predw[o*MID + c0 + cl] * g_ca[b*MID + c0 + cl];
            pw[cl][i % 28] = v;
        }
        __syncthreads();
        const float* yb = g_y + ((size_t)b*MID + c0)*HW + p;
        #pragma unroll 4
        for (int cl = 0; cl < 64; cl++) {
            float yv = yb[(size_t)cl*HW];
            const float4* pw4 = (const float4*)pw[cl];
            #pragma unroll
            for (int j = 0; j < 7; j++) {
                float4 w4 = pw4[j];
                acc[j].x += w4.x*yv; acc[j].y += w4.y*yv;
                acc[j].z += w4.z*yv; acc[j].w += w4.w*yv;
            }
        }
    }

    float mf = g_mf[b*HW + p];
    float* dbase = out + BOUT + ((size_t)b*OUTC)*HW + p;
    float* cnt   = out + b*OUTC;
    int lane = t & 31;

#define EMIT(OO, AV) do {                                              \
        if ((OO) < OUTC) {                                             \
            float dv = 1.f/(1.f + expf(-(AV)*mf));                     \
            dbase[(size_t)(OO)*HW] = dv;                               \
            float s_ = dv;                                             \
            s_ += __shfl_down_sync(0xffffffffu, s_, 16);               \
            s_ += __shfl_down_sync(0xffffffffu, s_, 8);                \
            s_ += __shfl_down_sync(0xffffffffu, s_, 4);                \
            s_ += __shfl_down_sync(0xffffffffu, s_, 2);                \
            s_ += __shfl_down_sync(0xffffffffu, s_, 1);                \
            if (lane == 0) atomicAdd(&cnt[(OO)], s_);                  \
        }                                                              \
    } while (0)

    #pragma unroll
    for (int j = 0; j < 7; j++) {
        float4 a = acc[j];
        EMIT(ob + 4*j+0, a.x); EMIT(ob + 4*j+1, a.y);
        EMIT(ob + 4*j+2, a.z); EMIT(ob + 4*j+3, a.w);
    }
#undef EMIT
}

extern "C" void kernel_launch(void* const* d_in, const int* in_sizes, int n_in,
                              void* d_out, int out_size) {
    const float* x        = (const float*)d_in[0];
    const float* mask     = (const float*)d_in[1];
    const float* w3       = (const float*)d_in[2];
    const float* w5       = (const float*)d_in[3];
    const float* w7       = (const float*)d_in[4];
    const float* router_w = (const float*)d_in[5];
    const float* router_b = (const float*)d_in[6];
    const float* fc1_w    = (const float*)d_in[7];
    const float* fc1_b    = (const float*)d_in[8];
    const float* fc2_w    = (const float*)d_in[9];
    const float* fc2_b    = (const float*)d_in[10];
    const float* mpw      = (const float*)d_in[11];
    const float* mpb      = (const float*)d_in[12];
    const float* pred_w   = (const float*)d_in[13];
    float* out = (float*)d_out;

    // fused prep: conv is the 4th launch (ncu capture slot)
    prep0_kernel<<<3040, 256>>>(out);
    prep1_kernel<<<Bn + 2048, 256>>>(x, router_w, router_b, w3, w5, w7);

    cudaFuncSetAttribute(prep2_kernel, cudaFuncAttributeMaxDynamicSharedMemorySize, FM_SMEM);
    prep2_kernel<<<784 + 512, 256, FM_SMEM>>>(x);

    cudaFuncSetAttribute(conv_mma, cudaFuncAttributeMaxDynamicSharedMemorySize, SMEM_CONV);
    conv_mma<<<dim3(8, 4, Bn), 512, SMEM_CONV>>>();

    mf_kernel<<<dim3(4, Bn), 256>>>(mask, mpw, mpb);
    ca_kernel<<<Bn, 512>>>(fc1_w, fc1_b, fc2_w, fc2_b);
    final_kernel<<<dim3(Bn, 8, 4), 128>>>(pred_w, out);
}

// round 17
// speedup vs baseline: 1.3032x; 1.1643x over previous
#include <cuda_runtime.h>
#include <cuda.h>
#include <cuda_bf16.h>
#include <math.h>
#include <stdint.h>

#define Bn    16
#define Cin   128
#define HW    1024
#define MID   512
#define OUTC  111
#define NE    4
#define BOUT  (Bn*OUTC)
#define NTOT  (49*MID*Cin)
#define APW   (49*4*8*512)
#define XPW2  (38*32*40)

__device__ __align__(1024) float    g_routing[Bn*NE];
__device__ __align__(1024) float    g_wm[(size_t)NE*NTOT];
__device__ __align__(1024) uint32_t g_ah[(size_t)Bn*APW];
__device__ __align__(1024) uint32_t g_al[(size_t)Bn*APW];
__device__ __align__(1024) uint32_t g_xh[(size_t)Bn*XPW2];
__device__ __align__(1024) uint32_t g_xl[(size_t)Bn*XPW2];
__device__ __align__(1024) float    g_y[(size_t)Bn*MID*HW];
__device__ float g_ymean[Bn*MID];
__device__ float g_mf[Bn*HW];
__device__ float g_ca[Bn*MID];
__device__ unsigned int g_maxA;
__device__ unsigned int g_maxB;

#define QSCALE 16200.0f
#define FMAGIC 12582912.0f

__device__ __forceinline__ uint32_t smem_u32(const void* p){
    uint32_t a; asm("{ .reg .u64 t; cvta.to.shared.u64 t, %1; cvt.u32.u64 %0, t; }"
                    : "=r"(a) : "l"(p)); return a;
}
__device__ __forceinline__ void cp16(uint32_t dst, const void* src){
    asm volatile("cp.async.cg.shared.global [%0], [%1], 16;" :: "r"(dst), "l"(src));
}
__device__ __forceinline__ void cpcommit(){
    asm volatile("cp.async.commit_group;" ::: "memory");
}
template<int N> __device__ __forceinline__ void cpwait(){
    asm volatile("cp.async.wait_group %0;" :: "n"(N) : "memory");
}
#define LDS128(r0,r1,r2,r3,addr) \
    asm volatile("ld.shared.v4.b32 {%0,%1,%2,%3}, [%4];" \
        : "=r"(r0),"=r"(r1),"=r"(r2),"=r"(r3) : "r"(addr))
#define LDS32(r0,addr) \
    asm volatile("ld.shared.b32 %0, [%1];" : "=r"(r0) : "r"(addr))
#define MMA_S8(d, a, b2) \
    asm volatile("mma.sync.aligned.m16n8k32.row.col.s32.s8.s8.s32 " \
        "{%0,%1,%2,%3}, {%4,%5,%6,%7}, {%8,%9}, {%0,%1,%2,%3};" \
        : "+r"((d)[0]),"+r"((d)[1]),"+r"((d)[2]),"+r"((d)[3]) \
        : "r"((a)[0]),"r"((a)[1]),"r"((a)[2]),"r"((a)[3]), \
          "r"((b2)[0]),"r"((b2)[1]))

__device__ __forceinline__ uint64_t pkf2(float lo, float hi){
    uint64_t r; asm("mov.b64 %0, {%1, %2};" : "=l"(r) : "f"(lo), "f"(hi)); return r;
}
__device__ __forceinline__ uint64_t ffma2(uint64_t a, uint64_t b, uint64_t c){
    uint64_t d; asm("fma.rn.f32x2 %0, %1, %2, %3;" : "=l"(d) : "l"(a), "l"(b), "l"(c));
    return d;
}
__device__ __forceinline__ void upk2(uint64_t v, uint32_t& a, uint32_t& b){
    asm("mov.b64 {%0, %1}, %2;" : "=r"(a), "=r"(b) : "l"(v));
}
__device__ __forceinline__ void q2d(float v, float inv, int& hi, int& lo){
    int q = __float2int_rn(v*inv);
    hi = (q + 64) >> 7;
    lo = q - (hi << 7);
}
__device__ __forceinline__ uint32_t pk4(int b0, int b1, int b2, int b3){
    return (uint32_t)(b0 & 0xFF) | ((uint32_t)(b1 & 0xFF) << 8) |
           ((uint32_t)(b2 & 0xFF) << 16) | ((uint32_t)(b3 & 0xFF) << 24);
}
__device__ __forceinline__ void wmax_red(float m, unsigned int* dst){
    #pragma unroll
    for (int off = 16; off; off >>= 1)
        m = fmaxf(m, __shfl_xor_sync(0xffffffffu, m, off));
    if ((threadIdx.x & 31) == 0) atomicMax(dst, __float_as_uint(m));
}

// ---- prep0 ------------------------------------------------------------------
__global__ void prep0_kernel(float* out) {
    size_t i = (size_t)blockIdx.x*256 + threadIdx.x;
    if (i < BOUT)   out[i] = 0.f;
    if (i < Bn*MID) g_ymean[i] = 0.f;
    if (i == 0) { g_maxA = 0u; g_maxB = 0u; }
    if (i < (size_t)Bn*XPW2) { g_xh[i] = 0u; g_xl[i] = 0u; }
}

// ---- prep1: routing + merge -------------------------------------------------
__global__ void __launch_bounds__(256)
prep1_kernel(const float* __restrict__ x,
             const float* __restrict__ rw, const float* __restrict__ rb,
             const float* __restrict__ w3, const float* __restrict__ w5,
             const float* __restrict__ w7) {
    int bx = blockIdx.x;
    int t = threadIdx.x;
    if (bx < Bn) {
        int b = bx;
        __shared__ float pooled[Cin];
        __shared__ float logit[NE];
        int warp = t >> 5, lane = t & 31;
        const float* xb = x + (size_t)b*Cin*HW;
        float mx = 0.f;
        for (int c = warp; c < Cin; c += 8) {
            float s = 0.f;
            for (int i = lane; i < HW; i += 32) {
                float v = xb[c*HW + i];
                s += v; mx = fmaxf(mx, fabsf(v));
            }
            #pragma unroll
            for (int off = 16; off; off >>= 1) s += __shfl_down_sync(0xffffffffu, s, off);
            if (lane == 0) pooled[c] = s * (1.0f/HW);
        }
        wmax_red(mx, &g_maxB);
        __syncthreads();
        if (t < NE) {
            float s = rb[t];
            for (int c = 0; c < Cin; c++) s += pooled[c] * rw[t*Cin + c];
            logit[t] = s;
        }
        __syncthreads();
        if (t == 0) {
            float m = fmaxf(fmaxf(logit[0],logit[1]), fmaxf(logit[2],logit[3]));
            float e[NE]; float sum = 0.f;
            #pragma unroll
            for (int i = 0; i < NE; i++) { e[i] = expf(logit[i]-m); sum += e[i]; }
            float inv = 1.f/sum;
            #pragma unroll
            for (int i = 0; i < NE; i++) g_routing[b*NE + i] = e[i]*inv;
        }
    } else {
        int idx = bx - Bn;
        int o = idx & 511, e = idx >> 9;
        __shared__ float s7[Cin*49];
        __shared__ float s5[Cin*25];
        __shared__ float s3[Cin*9];
        size_t base = ((size_t)e*MID + o)*Cin;
        for (int i = t; i < Cin*49; i += 256) s7[i] = w7[base*49 + i];
        for (int i = t; i < Cin*25; i += 256) s5[i] = w5[base*25 + i];
        for (int i = t; i < Cin*9;  i += 256) s3[i] = w3[base*9  + i];
        __syncthreads();
        float mx = 0.f;
        for (int i = t; i < 49*Cin; i += 256) {
            int tap = i >> 7, ic = i & 127;
            int ty = tap / 7, tx = tap % 7;
            float v = s7[ic*49 + tap];
            if ((unsigned)(ty-1) < 5u && (unsigned)(tx-1) < 5u) v += s5[ic*25 + (ty-1)*5 + (tx-1)];
            if ((unsigned)(ty-2) < 3u && (unsigned)(tx-2) < 3u) v += s3[ic*9  + (ty-2)*3 + (tx-2)];
            g_wm[(((size_t)e*49 + tap)*MID + o)*Cin + ic] = v;
            mx = fmaxf(mx, fabsf(v));
        }
        wmax_red(mx, &g_maxA);
    }
}

// ---- prep2: fragmix + xp_fill -----------------------------------------------
#define FM_SMEM (4*128*33*4)
__global__ void __launch_bounds__(256)
prep2_kernel(const float* __restrict__ x) {
    extern __shared__ float ws[];
    int bx = blockIdx.x;
    int tid = threadIdx.x;
    if (bx < 784) {
        __shared__ float r[Bn*NE];
        int t = bx % 49, yy = bx / 49;
        int icq = yy & 3, mtb4 = yy >> 2;
        if (tid < Bn*NE) r[tid] = g_routing[tid];
        for (int idx = tid; idx < 4*128*32; idx += 256) {
            int e = idx >> 12, ol = (idx >> 5) & 127, icl = idx & 31;
            ws[(e*128 + ol)*33 + icl] =
                g_wm[(((size_t)e*49 + t)*MID + mtb4*128 + ol)*Cin + icq*32 + icl];
        }
        __syncthreads();
        float invq = QSCALE / __uint_as_float(g_maxA);
        uint64_t IQ2 = pkf2(invq, invq);
        uint64_t IH2 = pkf2(invq*(1.0f/128.0f), invq*(1.0f/128.0f));
        uint64_t M2  = pkf2(FMAGIC, FMAGIC);

        int half = tid >> 7, mt = (tid >> 5) & 3, ln = tid & 31;
        int c = ln & 3, rl = ln >> 2;
        int oL = half*64 + mt*16 + rl;
        int kb = 4*c;
        uint64_t evp[8][4];
        #pragma unroll
        for (int e = 0; e < 4; e++) {
            int b0 = (e*128 + oL)*33;
            int b1 = b0 + 8*33;
            evp[0][e] = pkf2(ws[b0+kb],      ws[b0+kb+1]);
            evp[1][e] = pkf2(ws[b0+kb+2],    ws[b0+kb+3]);
            evp[2][e] = pkf2(ws[b1+kb],      ws[b1+kb+1]);
            evp[3][e] = pkf2(ws[b1+kb+2],    ws[b1+kb+3]);
            evp[4][e] = pkf2(ws[b0+16+kb],   ws[b0+16+kb+1]);
            evp[5][e] = pkf2(ws[b0+16+kb+2], ws[b0+16+kb+3]);
            evp[6][e] = pkf2(ws[b1+16+kb],   ws[b1+16+kb+1]);
            evp[7][e] = pkf2(ws[b1+16+kb+2], ws[b1+16+kb+3]);
        }
        size_t chunk = ((size_t)t*4 + icq)*8 + mtb4*2 + half;
        size_t dstw = chunk*512 + (size_t)(mt*32 + ln)*4;
        #pragma unroll
        for (int b = 0; b < Bn; b++) {
            uint64_t rp0 = pkf2(r[b*4+0], r[b*4+0]);
            uint64_t rp1 = pkf2(r[b*4+1], r[b*4+1]);
            uint64_t rp2 = pkf2(r[b*4+2], r[b*4+2]);
            uint64_t rp3 = pkf2(r[b*4+3], r[b*4+3]);
            uint32_t hw[4], lw[4];
            #pragma unroll
            for (int w = 0; w < 4; w++) {
                uint32_t hb[4], lb[4];
                #pragma unroll
                for (int pp = 0; pp < 2; pp++) {
                    int p = w*2 + pp;
                    uint64_t v2 = ffma2(evp[p][3], rp3, 0ull);
                    v2 = ffma2(evp[p][2], rp2, v2);
                    v2 = ffma2(evp[p][1], rp1, v2);
                    v2 = ffma2(evp[p][0], rp0, v2);
                    uint64_t hf2 = ffma2(v2, IH2, M2);
                    uint64_t qf2 = ffma2(v2, IQ2, M2);
                    uint32_t h0, h1, q0, q1;
                    upk2(hf2, h0, h1);
                    upk2(qf2, q0, q1);
                    hb[pp*2]   = h0;
                    hb[pp*2+1] = h1;
                    lb[pp*2]   = q0 - 128u*h0;
                    lb[pp*2+1] = q1 - 128u*h1;
                }
                hw[w] = __byte_perm(__byte_perm(hb[0], hb[1], 0x0040),
                                    __byte_perm(hb[2], hb[3], 0x0040), 0x5410);
                lw[w] = __byte_perm(__byte_perm(lb[0], lb[1], 0x0040),
                                    __byte_perm(lb[2], lb[3], 0x0040), 0x5410);
            }
            *(uint4*)&g_ah[(size_t)b*APW + dstw] = make_uint4(hw[0], hw[1], hw[2], hw[3]);
            *(uint4*)&g_al[(size_t)b*APW + dstw] = make_uint4(lw[0], lw[1], lw[2], lw[3]);
        }
    } else {
        int idx = bx - 784;
        int b = idx >> 5, h = idx & 31;
        int w = tid & 31, grp = tid >> 5;
        float inv = QSCALE / __uint_as_float(g_maxB);
        #pragma unroll
        for (int i = 0; i < 4; i++) {
            int k4 = grp + i*8;
            int hh[4], ll[4];
            #pragma unroll
            for (int j = 0; j < 4; j++) {
                float v = x[((size_t)b*Cin + 4*k4 + j)*HW + h*32 + w];
                q2d(v, inv, hh[j], ll[j]);
            }
            size_t d = (((size_t)b*38 + h + 3)*32 + k4)*40 + w + 3;
            g_xh[d] = pk4(hh[0], hh[1], hh[2], hh[3]);
            g_xl[d] = pk4(ll[0], ll[1], ll[2], ll[3]);
        }
    }
}

// ---------------- conv: int8 IMMA, M=64 N=128, 256 threads, 2 CTAs/SM ---------
#define A_LO      2048
#define A_STG     4096
#define A_ALL     (4*A_STG)                 // 16384
#define B_ISTR    168                       // k4 stride in words (==8 mod 32)
#define B_STG     5376                      // 8*168*4 bytes per plane
#define B_STG2    (2*B_STG)                 // 10752
#define SMEM_CONV (A_ALL + 2*B_STG2)        // 37888

__global__ void __launch_bounds__(256, 2)
conv_mma() {
    extern __shared__ __align__(16) char smem[];
    uint32_t sb = smem_u32(smem);
    int tid = threadIdx.x, wid = tid >> 5, lane = tid & 31;
    int c = lane & 3, rl = lane >> 2;
    int wm = wid & 1, wn = wid >> 1;       // 2 (m) x 4 (n)
    int mtb = blockIdx.x, nt = blockIdx.y, b = blockIdx.z;

    const uint32_t* Abh = g_ah + (size_t)b*APW;
    const uint32_t* Abl = g_al + (size_t)b*APW;

    int acc1[2][4][4], acc2[2][4][4];
    #pragma unroll
    for (int mi = 0; mi < 2; mi++)
        #pragma unroll
        for (int ni = 0; ni < 4; ni++)
            #pragma unroll
            for (int q = 0; q < 4; q++) { acc1[mi][ni][q] = 0; acc2[mi][ni][q] = 0; }

    uint32_t bb[4];
    #pragma unroll
    for (int ni = 0; ni < 4; ni++) {
        int p = wn*32 + ni*8 + rl;          // 0..127
        bb[ni] = (uint32_t)((((p >> 5)*40) + (p & 31)) << 2);
    }

    auto issueA = [&](int m, int buf) {
        int jj = m/7, dxx = m - jj*7;
        int t = (jj >> 2)*7 + dxx, icq = jj & 3;
        size_t chunk = ((size_t)t*4 + icq)*8 + mtb;
        int half = tid >> 7, u = tid & 127;
        const uint32_t* src = (half ? Abl : Abh) + chunk*512 + (size_t)u*4;
        uint32_t dst = sb + buf*A_STG + (uint32_t)(half*A_LO) + (uint32_t)(u*16);
        cp16(dst, src);
    };
    auto issueB = [&](int jj, int buf) {
        int dy = jj >> 2, icq = jj & 3;
        for (int task = tid; task < 640; task += 256) {
            int plane = task >= 320;
            int v = plane ? task - 320 : task;
            int k4 = v / 40, rem = v % 40;
            int h = rem / 10, q = rem % 10;
            size_t srcw = (((size_t)(b*38 + nt*4 + h + dy))*32 + icq*8 + k4)*40 + q*4;
            const uint32_t* src = plane ? (g_xl + srcw) : (g_xh + srcw);
            uint32_t dst = sb + A_ALL + buf*B_STG2 + (uint32_t)(plane*B_STG)
                         + (uint32_t)(k4*672 + h*160 + q*16);
            cp16(dst, src);
        }
    };

    issueB(0, 0); issueA(0, 0); cpcommit();
    issueA(1, 1); cpcommit();
    issueA(2, 2); cpcommit();

    int j = 0, dx = 0;
    for (int m = 0; m < 196; m++) {
        if (m < 194)        cpwait<2>();
        else if (m == 194)  cpwait<1>();
        else                cpwait<0>();
        __syncthreads();
        {
            bool any = false;
            if (m + 3 < 196) { issueA(m + 3, (m + 3) & 3); any = true; }
            if (dx == 0 && j < 27) { issueB(j + 1, (j + 1) & 1); any = true; }
            if (any) cpcommit();
        }

        uint32_t aS  = sb + (m & 3)*A_STG;
        uint32_t bSh = sb + A_ALL + (j & 1)*B_STG2 + (uint32_t)(dx << 2);
        uint32_t bSl = bSh + B_STG;
        uint32_t k0o = (uint32_t)(c*672), k1o = k0o + 4*672;

        uint32_t bh[4][2], bl[4][2];
        #pragma unroll
        for (int ni = 0; ni < 4; ni++) {
            LDS32(bh[ni][0], bSh + k0o + bb[ni]);
            LDS32(bh[ni][1], bSh + k1o + bb[ni]);
            LDS32(bl[ni][0], bSl + k0o + bb[ni]);
            LDS32(bl[ni][1], bSl + k1o + bb[ni]);
        }
        uint32_t af[2][4];
        #pragma unroll
        for (int mi = 0; mi < 2; mi++)
            LDS128(af[mi][0], af[mi][1], af[mi][2], af[mi][3],
                   aS + (uint32_t)((((wm*2 + mi)*32) + lane) << 4));
        #pragma unroll
        for (int mi = 0; mi < 2; mi++)
            #pragma unroll
            for (int ni = 0; ni < 4; ni++) {
                MMA_S8(acc1[mi][ni], af[mi], bh[ni]);
                MMA_S8(acc2[mi][ni], af[mi], bl[ni]);
            }
        #pragma unroll
        for (int mi = 0; mi < 2; mi++)
            LDS128(af[mi][0], af[mi][1], af[mi][2], af[mi][3],
                   aS + A_LO + (uint32_t)((((wm*2 + mi)*32) + lane) << 4));
        #pragma unroll
        for (int mi = 0; mi < 2; mi++)
            #pragma unroll
            for (int ni = 0; ni < 4; ni++)
                MMA_S8(acc2[mi][ni], af[mi], bh[ni]);

        if (++dx == 7) { dx = 0; j++; }
    }

    float S = (__uint_as_float(g_maxA)/QSCALE) * (__uint_as_float(g_maxB)/QSCALE);
    int o0 = mtb*64 + wm*32;
    int p0 = nt*128 + wn*32;
    #pragma unroll
    for (int mi = 0; mi < 2; mi++) {
        int o = o0 + mi*16 + rl;
        float s0 = 0.f, s1 = 0.f;
        float* y0 = g_y + ((size_t)b*MID + o)*HW;
        float* y1 = g_y + ((size_t)b*MID + o + 8)*HW;
        #pragma unroll
        for (int ni = 0; ni < 4; ni++) {
            int p = p0 + ni*8 + 2*c;
            float2 v0, v1;
            v0.x = S*(16384.f*(float)acc1[mi][ni][0] + 128.f*(float)acc2[mi][ni][0]);
            v0.y = S*(16384.f*(float)acc1[mi][ni][1] + 128.f*(float)acc2[mi][ni][1]);
            v1.x = S*(16384.f*(float)acc1[mi][ni][2] + 128.f*(float)acc2[mi][ni][2]);
            v1.y = S*(16384.f*(float)acc1[mi][ni][3] + 128.f*(float)acc2[mi][ni][3]);
            *(float2*)(y0 + p) = v0;
            *(float2*)(y1 + p) = v1;
            s0 += v0.x + v0.y;
            s1 += v1.x + v1.y;
        }
        s0 += __shfl_xor_sync(0xffffffffu, s0, 1);
        s0 += __shfl_xor_sync(0xffffffffu, s0, 2);
        s1 += __shfl_xor_sync(0xffffffffu, s1, 1);
        s1 += __shfl_xor_sync(0xffffffffu, s1, 2);
        if (c == 0) {
            atomicAdd(&g_ymean[b*MID + o], s0);
            atomicAdd(&g_ymean[b*MID + o + 8], s1);
        }
    }
}

__global__ void ca_kernel(const float* __restrict__ fc1w, const float* __restrict__ fc1b,
                          const float* __restrict__ fc2w, const float* __restrict__ fc2b) {
    int b = blockIdx.x, t = threadIdx.x;
    __shared__ float m[MID];
    __shared__ float h[32];
    m[t] = g_ymean[b*MID + t] * (1.0f/HW);
    __syncthreads();
    if (t < 32) {
        float s = fc1b[t];
        for (int c = 0; c < MID; c++) s += fc1w[t*MID + c] * m[c];
        h[t] = fmaxf(s, 0.f);
    }
    __syncthreads();
    float s = fc2b[t];
    #pragma unroll
    for (int j = 0; j < 32; j++) s += fc2w[t*32 + j] * h[j];
    g_ca[b*MID + t] = 1.f/(1.f + expf(-s));
}

__global__ void mf_kernel(const float* __restrict__ mask,
                          const float* __restrict__ mpw,
                          const float* __restrict__ mpb) {
    __shared__ float w[Cin];
    int t = threadIdx.x;
    if (t < Cin) w[t] = mpw[t];
    __syncthreads();
    int b = blockIdx.y;
    int p = blockIdx.x*256 + t;
    const float* mb = mask + (size_t)b*Cin*HW + p;
    float s = mpb[0];
    #pragma unroll 8
    for (int c = 0; c < Cin; c++) s += mb[c*HW] * w[c];
    g_mf[b*HW + p] = s;
}

__global__ void __launch_bounds__(128)
final_kernel(const float* __restrict__ predw, float* __restrict__ out) {
    int b = blockIdx.x, pt = blockIdx.y, oq = blockIdx.z;
    int t = threadIdx.x;
    int p = pt*128 + t;
    int ob = oq*28;

    __shared__ float pw[64][28];
    float4 acc[7];
    #pragma unroll
    for (int j = 0; j < 7; j++) acc[j] = make_float4(0.f,0.f,0.f,0.f);

    for (int c0 = 0; c0 < MID; c0 += 64) {
        __syncthreads();
        for (int i = t; i < 64*28; i += 128) {
            int cl = i / 28, o = ob + i % 28;
            float v = 0.f;
            if (o < OUTC) v = predw[o*MID + c0 + cl] * g_ca[b*MID + c0 + cl];
            pw[cl][i % 28] = v;
        }
        __syncthreads();
        const float* yb = g_y + ((size_t)b*MID + c0)*HW + p;
        #pragma unroll 4
        for (int cl = 0; cl < 64; cl++) {
            float yv = yb[(size_t)cl*HW];
            const float4* pw4 = (const float4*)pw[cl];
            #pragma unroll
            for (int j = 0; j < 7; j++) {
                float4 w4 = pw4[j];
                acc[j].x += w4.x*yv; acc[j].y += w4.y*yv;
                acc[j].z += w4.z*yv; acc[j].w += w4.w*yv;
            }
        }
    }

    float mf = g_mf[b*HW + p];
    float* dbase = out + BOUT + ((size_t)b*OUTC)*HW + p;
    float* cnt   = out + b*OUTC;
    int lane = t & 31;

#define EMIT(OO, AV) do {                                              \
        if ((OO) < OUTC) {                                             \
            float dv = 1.f/(1.f + expf(-(AV)*mf));                     \
            dbase[(size_t)(OO)*HW] = dv;                               \
            float s_ = dv;                                             \
            s_ += __shfl_down_sync(0xffffffffu, s_, 16);               \
            s_ += __shfl_down_sync(0xffffffffu, s_, 8);                \
            s_ += __shfl_down_sync(0xffffffffu, s_, 4);                \
            s_ += __shfl_down_sync(0xffffffffu, s_, 2);                \
            s_ += __shfl_down_sync(0xffffffffu, s_, 1);                \
            if (lane == 0) atomicAdd(&cnt[(OO)], s_);                  \
        }                                                              \
    } while (0)

    #pragma unroll
    for (int j = 0; j < 7; j++) {
        float4 a = acc[j];
        EMIT(ob + 4*j+0, a.x); EMIT(ob + 4*j+1, a.y);
        EMIT(ob + 4*j+2, a.z); EMIT(ob + 4*j+3, a.w);
    }
#undef EMIT
}

extern "C" void kernel_launch(void* const* d_in, const int* in_sizes, int n_in,
                              void* d_out, int out_size) {
    const float* x        = (const float*)d_in[0];
    const float* mask     = (const float*)d_in[1];
    const float* w3       = (const float*)d_in[2];
    const float* w5       = (const float*)d_in[3];
    const float* w7       = (const float*)d_in[4];
    const float* router_w = (const float*)d_in[5];
    const float* router_b = (const float*)d_in[6];
    const float* fc1_w    = (const float*)d_in[7];
    const float* fc1_b    = (const float*)d_in[8];
    const float* fc2_w    = (const float*)d_in[9];
    const float* fc2_b    = (const float*)d_in[10];
    const float* mpw      = (const float*)d_in[11];
    const float* mpb      = (const float*)d_in[12];
    const float* pred_w   = (const float*)d_in[13];
    float* out = (float*)d_out;

    prep0_kernel<<<3040, 256>>>(out);
    prep1_kernel<<<Bn + 2048, 256>>>(x, router_w, router_b, w3, w5, w7);

    cudaFuncSetAttribute(prep2_kernel, cudaFuncAttributeMaxDynamicSharedMemorySize, FM_SMEM);
    prep2_kernel<<<784 + 512, 256, FM_SMEM>>>(x);

    cudaFuncSetAttribute(conv_mma, cudaFuncAttributeMaxDynamicSharedMemorySize, SMEM_CONV);
    conv_mma<<<dim3(8, 8, Bn), 256, SMEM_CONV>>>();

    mf_kernel<<<dim3(4, Bn), 256>>>(mask, mpw, mpb);
    ca_kernel<<<Bn, 512>>>(fc1_w, fc1_b, fc2_w, fc2_b);
    final_kernel<<<dim3(Bn, 8, 4), 128>>>(pred_w, out);
}